// round 2
// baseline (speedup 1.0000x reference)
#include <cuda_runtime.h>
#include <math.h>

// ---------------- problem constants ----------------
#define BK   384      // 48 * K
#define BB   48
#define KK   8
#define HH   250
#define EPSL 1e-5f

// ---------------- scratch (device globals, no allocs) ----------------
__device__ float g_e1[BK*32*32*16];     // conv1 out
__device__ float g_e2[BK*16*16*32];     // conv2 out
__device__ float g_e3[BK*8*8*64];       // conv3 out (= 4096 per row)
__device__ float g_h [BK*512];          // efc out
__device__ float g_s1[BK*HH];           // renc out
__device__ float g_pair[BB*KK*7*(2*HH)];// 2688 x 500
__device__ float g_core[BB*KK*7*HH];    // 2688 x 250
__device__ float g_ctx [BB*KK*7*HH];
__device__ float g_a1  [BB*KK*7*100];
__device__ float g_att [BB*KK*7];
__device__ float g_eff [BK*HH];
__device__ float g_tot [BK*(2*HH+512)]; // 384 x 1012
__device__ float g_ns  [BK*HH];
__device__ float g_xr  [BK*HH];
__device__ float g_d512[BK*512];
__device__ float g_d4096[BK*4096];
__device__ float g_u1[BK*16*16*32];     // dec1 out
__device__ float g_u2[BK*32*32*16];     // dec2 out

// ---------------- helpers ----------------
__device__ __forceinline__ void block_reduce2(float& a, float& b) {
    __shared__ float sa[32], sb[32];
    const unsigned m = 0xffffffffu;
    for (int o = 16; o > 0; o >>= 1) { a += __shfl_down_sync(m, a, o); b += __shfl_down_sync(m, b, o); }
    int lane = threadIdx.x & 31, wid = threadIdx.x >> 5;
    if (lane == 0) { sa[wid] = a; sb[wid] = b; }
    __syncthreads();
    int nw = (blockDim.x + 31) >> 5;
    if (wid == 0) {
        a = (lane < nw) ? sa[lane] : 0.f;
        b = (lane < nw) ? sb[lane] : 0.f;
        for (int o = 16; o > 0; o >>= 1) { a += __shfl_down_sync(m, a, o); b += __shfl_down_sync(m, b, o); }
        if (lane == 0) { sa[0] = a; sb[0] = b; }
    }
    __syncthreads();
    a = sa[0]; b = sb[0];
    __syncthreads();
}

__device__ __forceinline__ float sigm(float v) { return 1.f / (1.f + expf(-v)); }

// ---------------- encoder conv: out[n,a',b',o] = b[o] + sum L[n,2a'-1+kw,2b'-1+kh,i] w[o,i,kh,kw]
template<int CIN, int COUT, int WOUT>
__global__ void enc_conv(const float* __restrict__ in, const float* __restrict__ w,
                         const float* __restrict__ bias, float* __restrict__ out) {
    const int WIN = 2 * WOUT;
    const int total = BK * WOUT * WOUT * COUT;
    for (int idx = blockIdx.x * blockDim.x + threadIdx.x; idx < total; idx += gridDim.x * blockDim.x) {
        int o = idx % COUT;  int t = idx / COUT;
        int bp = t % WOUT;   t /= WOUT;
        int ap = t % WOUT;   int n = t / WOUT;
        float acc = bias[o];
        #pragma unroll
        for (int kw = 0; kw < 4; kw++) {
            int a = 2 * ap - 1 + kw;
            if (a < 0 || a >= WIN) continue;
            #pragma unroll
            for (int kh = 0; kh < 4; kh++) {
                int bb = 2 * bp - 1 + kh;
                if (bb < 0 || bb >= WIN) continue;
                const float* ip = in + ((size_t)(n * WIN + a) * WIN + bb) * CIN;
                const float* wp = w + ((size_t)o * CIN * 4 + kh) * 4 + kw;
                #pragma unroll 4
                for (int i = 0; i < CIN; i++) acc += ip[i] * wp[(size_t)i * 16];
            }
        }
        out[idx] = acc;
    }
}

// ---------------- decoder conv (up4 folded): src pixel = L[n,(2a'-1+kw)/4,(2b'-1+kh)/4,i]
template<int CIN, int COUT, int WIN, bool SIG>
__global__ void dec_conv(const float* __restrict__ in, const float* __restrict__ w,
                         const float* __restrict__ bias, float* __restrict__ out) {
    const int WOUT = 2 * WIN;
    const int UP = 4 * WIN;
    const int total = BK * WOUT * WOUT * COUT;
    for (int idx = blockIdx.x * blockDim.x + threadIdx.x; idx < total; idx += gridDim.x * blockDim.x) {
        int o = idx % COUT;  int t = idx / COUT;
        int bp = t % WOUT;   t /= WOUT;
        int ap = t % WOUT;   int n = t / WOUT;
        float acc = bias[o];
        #pragma unroll
        for (int kw = 0; kw < 4; kw++) {
            int a = 2 * ap - 1 + kw;
            if (a < 0 || a >= UP) continue;
            int as = a >> 2;
            #pragma unroll
            for (int kh = 0; kh < 4; kh++) {
                int bb = 2 * bp - 1 + kh;
                if (bb < 0 || bb >= UP) continue;
                int bs = bb >> 2;
                const float* ip = in + ((size_t)(n * WIN + as) * WIN + bs) * CIN;
                const float* wp = w + ((size_t)o * CIN * 4 + kh) * 4 + kw;
                #pragma unroll 4
                for (int i = 0; i < CIN; i++) acc += ip[i] * wp[(size_t)i * 16];
            }
        }
        out[idx] = SIG ? sigm(acc) : acc;
    }
}

// ---------------- LayerNorm (last-dim or all-dims via C) + activation ----------------
// mode: 0=elu 1=relu 2=tanh
__global__ void ln_act(const float* __restrict__ in, float* __restrict__ out, int C, int mode) {
    int r = blockIdx.x;
    const float* x = in + (size_t)r * C;
    float s = 0.f, ss = 0.f;
    for (int c = threadIdx.x; c < C; c += blockDim.x) { float v = x[c]; s += v; ss += v * v; }
    block_reduce2(s, ss);
    float mean = s / C;
    float var = ss / C - mean * mean;
    float inv = rsqrtf(var + EPSL);
    float* y = out + (size_t)r * C;
    for (int c = threadIdx.x; c < C; c += blockDim.x) {
        float v = (x[c] - mean) * inv;
        if (mode == 0)      v = (v > 0.f) ? v : expm1f(v);
        else if (mode == 1) v = fmaxf(v, 0.f);
        else                v = tanhf(v);
        y[c] = v;
    }
}

// ---------------- tiled GEMM: Y[M,N] = X[M,K] @ W[K,N] + b[N] ----------------
__global__ void gemm_bias(const float* __restrict__ X, const float* __restrict__ W,
                          const float* __restrict__ bias, float* __restrict__ Y,
                          int M, int N, int Kd) {
    __shared__ float Xs[16][16];
    __shared__ float Ws[16][17];
    int row = blockIdx.y * 16 + threadIdx.y;
    int col = blockIdx.x * 16 + threadIdx.x;
    float acc = 0.f;
    for (int k0 = 0; k0 < Kd; k0 += 16) {
        int kx = k0 + threadIdx.x;
        Xs[threadIdx.y][threadIdx.x] = (row < M && kx < Kd) ? X[(size_t)row * Kd + kx] : 0.f;
        int ky = k0 + threadIdx.y;
        Ws[threadIdx.y][threadIdx.x] = (ky < Kd && col < N) ? W[(size_t)ky * N + col] : 0.f;
        __syncthreads();
        #pragma unroll
        for (int kk = 0; kk < 16; kk++) acc += Xs[threadIdx.y][kk] * Ws[kk][threadIdx.x];
        __syncthreads();
    }
    if (row < M && col < N) Y[(size_t)row * N + col] = acc + bias[col];
}

// ---------------- pair build: rows 2688, cols 500 ----------------
__global__ void build_pair(const float* __restrict__ s1, float* __restrict__ pair) {
    const int total = BB * KK * 7 * (2 * HH);
    for (int idx = blockIdx.x * blockDim.x + threadIdx.x; idx < total; idx += gridDim.x * blockDim.x) {
        int c = idx % (2 * HH);
        int r = idx / (2 * HH);
        int j = r % 7;  int t = r / 7;
        int i = t % KK; int bq = t / KK;
        int jj = (j < i) ? j : j + 1;
        float v;
        if (c < HH) v = s1[(size_t)(bq * KK + i) * HH + c];
        else        v = s1[(size_t)(bq * KK + jj) * HH + (c - HH)];
        pair[idx] = v;
    }
}

// ---------------- att2: warp-per-row dot(100) + sigmoid ----------------
__global__ void att2_kernel(const float* __restrict__ a1, const float* __restrict__ w2,
                            const float* __restrict__ b2, float* __restrict__ att, int R) {
    int r = blockIdx.x * 4 + (threadIdx.x >> 5);
    int lane = threadIdx.x & 31;
    if (r >= R) return;
    float s = 0.f;
    for (int c = lane; c < 100; c += 32) s += a1[(size_t)r * 100 + c] * w2[c];
    for (int o = 16; o > 0; o >>= 1) s += __shfl_down_sync(0xffffffffu, s, o);
    if (lane == 0) att[r] = sigm(s + b2[0]);
}

// ---------------- effect: sum over j of ctx*att ----------------
__global__ void effect_kernel(const float* __restrict__ ctx, const float* __restrict__ att,
                              float* __restrict__ eff) {
    int idx = blockIdx.x * blockDim.x + threadIdx.x;
    if (idx >= BK * HH) return;
    int h = idx % HH;
    int rbk = idx / HH;  // b*8+i
    float acc = 0.f;
    #pragma unroll
    for (int j = 0; j < 7; j++) {
        int r = rbk * 7 + j;
        acc += ctx[(size_t)r * HH + h] * att[r];
    }
    eff[idx] = acc;
}

// ---------------- total build: [s1 | effect | h] -> 384x1012 ----------------
__global__ void build_total(const float* __restrict__ s1, const float* __restrict__ eff,
                            const float* __restrict__ h, float* __restrict__ tot) {
    const int CT = 2 * HH + 512;
    const int total = BK * CT;
    for (int idx = blockIdx.x * blockDim.x + threadIdx.x; idx < total; idx += gridDim.x * blockDim.x) {
        int c = idx % CT;
        int r = idx / CT;
        float v;
        if (c < HH)            v = s1[(size_t)r * HH + c];
        else if (c < 2 * HH)   v = eff[(size_t)r * HH + (c - HH)];
        else                   v = h[(size_t)r * 512 + (c - 2 * HH)];
        tot[idx] = v;
    }
}

// ---------------- xr = sigmoid(ln(ns)); state_out = sigmoid(ns) ----------------
__global__ void xr_state_kernel(const float* __restrict__ ns, float* __restrict__ xr,
                                float* __restrict__ st_out) {
    int r = blockIdx.x;
    const float* x = ns + (size_t)r * HH;
    float s = 0.f, ss = 0.f;
    for (int c = threadIdx.x; c < HH; c += blockDim.x) { float v = x[c]; s += v; ss += v * v; }
    block_reduce2(s, ss);
    float mean = s / HH;
    float var = ss / HH - mean * mean;
    float inv = rsqrtf(var + EPSL);
    for (int c = threadIdx.x; c < HH; c += blockDim.x) {
        float v = x[c];
        xr[(size_t)r * HH + c] = sigm((v - mean) * inv);
        st_out[(size_t)r * HH + c] = sigm(v);
    }
}

// ---------------- host side ----------------
static inline int nblk(long long total, int bs) { return (int)((total + bs - 1) / bs); }

extern "C" void kernel_launch(void* const* d_in, const int* in_sizes, int n_in,
                              void* d_out, int out_size) {
    const float* x      = (const float*)d_in[0];
    const float* state  = (const float*)d_in[1];
    const float* c1w = (const float*)d_in[2];  const float* c1b = (const float*)d_in[3];
    const float* c2w = (const float*)d_in[4];  const float* c2b = (const float*)d_in[5];
    const float* c3w = (const float*)d_in[6];  const float* c3b = (const float*)d_in[7];
    const float* efc_w = (const float*)d_in[8];  const float* efc_b = (const float*)d_in[9];
    const float* renc_w = (const float*)d_in[10]; const float* renc_b = (const float*)d_in[11];
    const float* core_w = (const float*)d_in[12]; const float* core_b = (const float*)d_in[13];
    const float* ctx_w  = (const float*)d_in[14]; const float* ctx_b  = (const float*)d_in[15];
    const float* att1_w = (const float*)d_in[16]; const float* att1_b = (const float*)d_in[17];
    const float* att2_w = (const float*)d_in[18]; const float* att2_b = (const float*)d_in[19];
    const float* out_w  = (const float*)d_in[20]; const float* out_b  = (const float*)d_in[21];
    const float* dfc1_w = (const float*)d_in[22]; const float* dfc1_b = (const float*)d_in[23];
    const float* dfc2_w = (const float*)d_in[24]; const float* dfc2_b = (const float*)d_in[25];
    const float* d1w = (const float*)d_in[26]; const float* d1b = (const float*)d_in[27];
    const float* d2w = (const float*)d_in[28]; const float* d2b = (const float*)d_in[29];
    const float* d3w = (const float*)d_in[30]; const float* d3b = (const float*)d_in[31];

    float* out_x  = (float*)d_out;                    // 384*4096
    float* out_st = (float*)d_out + (size_t)BK * 4096; // 384*250

    float* e1 = nullptr, *e2 = nullptr, *e3 = nullptr, *h = nullptr, *s1 = nullptr;
    float* pair = nullptr, *core = nullptr, *ctx = nullptr, *a1 = nullptr, *att = nullptr;
    float* eff = nullptr, *tot = nullptr, *ns = nullptr, *xr = nullptr;
    float* d512 = nullptr, *d4096 = nullptr, *u1 = nullptr, *u2 = nullptr;
    cudaGetSymbolAddress((void**)&e1, g_e1);   cudaGetSymbolAddress((void**)&e2, g_e2);
    cudaGetSymbolAddress((void**)&e3, g_e3);   cudaGetSymbolAddress((void**)&h, g_h);
    cudaGetSymbolAddress((void**)&s1, g_s1);   cudaGetSymbolAddress((void**)&pair, g_pair);
    cudaGetSymbolAddress((void**)&core, g_core); cudaGetSymbolAddress((void**)&ctx, g_ctx);
    cudaGetSymbolAddress((void**)&a1, g_a1);   cudaGetSymbolAddress((void**)&att, g_att);
    cudaGetSymbolAddress((void**)&eff, g_eff); cudaGetSymbolAddress((void**)&tot, g_tot);
    cudaGetSymbolAddress((void**)&ns, g_ns);   cudaGetSymbolAddress((void**)&xr, g_xr);
    cudaGetSymbolAddress((void**)&d512, g_d512); cudaGetSymbolAddress((void**)&d4096, g_d4096);
    cudaGetSymbolAddress((void**)&u1, g_u1);   cudaGetSymbolAddress((void**)&u2, g_u2);

    const int BS = 256;

    // ---- encoder ----
    enc_conv<1, 16, 32><<<nblk((long long)BK*32*32*16, BS), BS>>>(x, c1w, c1b, e1);
    ln_act<<<BK, BS>>>(e1, e1, 32*32*16, 0);
    enc_conv<16, 32, 16><<<nblk((long long)BK*16*16*32, BS), BS>>>(e1, c2w, c2b, e2);
    ln_act<<<BK, BS>>>(e2, e2, 16*16*32, 0);
    enc_conv<32, 64, 8><<<nblk((long long)BK*8*8*64, BS), BS>>>(e2, c3w, c3b, e3);
    ln_act<<<BK, BS>>>(e3, e3, 8*8*64, 0);

    {   dim3 g((512 + 15) / 16, (BK + 15) / 16), b(16, 16);
        gemm_bias<<<g, b>>>(e3, efc_w, efc_b, h, BK, 512, 4096); }
    ln_act<<<BK, BS>>>(h, h, 512, 0);

    // ---- recurrent / attention core ----
    {   dim3 g((HH + 15) / 16, (BK + 15) / 16), b(16, 16);
        gemm_bias<<<g, b>>>(state, renc_w, renc_b, s1, BK, HH, HH); }
    ln_act<<<BK, BS>>>(s1, s1, HH, 1);

    build_pair<<<nblk((long long)BB*KK*7*(2*HH), BS), BS>>>(s1, pair);

    const int R = BB * KK * 7; // 2688
    {   dim3 g((HH + 15) / 16, (R + 15) / 16), b(16, 16);
        gemm_bias<<<g, b>>>(pair, core_w, core_b, core, R, HH, 2 * HH); }
    ln_act<<<R, BS>>>(core, core, HH, 1);

    {   dim3 g((HH + 15) / 16, (R + 15) / 16), b(16, 16);
        gemm_bias<<<g, b>>>(core, ctx_w, ctx_b, ctx, R, HH, HH); }
    ln_act<<<R, BS>>>(ctx, ctx, HH, 1);

    {   dim3 g((100 + 15) / 16, (R + 15) / 16), b(16, 16);
        gemm_bias<<<g, b>>>(core, att1_w, att1_b, a1, R, 100, HH); }
    ln_act<<<R, BS>>>(a1, a1, 100, 2);

    att2_kernel<<<(R + 3) / 4, 128>>>(a1, att2_w, att2_b, att, R);
    effect_kernel<<<nblk((long long)BK*HH, BS), BS>>>(ctx, att, eff);

    build_total<<<nblk((long long)BK*(2*HH+512), BS), BS>>>(s1, eff, h, tot);
    {   dim3 g((HH + 15) / 16, (BK + 15) / 16), b(16, 16);
        gemm_bias<<<g, b>>>(tot, out_w, out_b, ns, BK, HH, 2 * HH + 512); }

    xr_state_kernel<<<BK, BS>>>(ns, xr, out_st);

    // ---- decoder ----
    {   dim3 g((512 + 15) / 16, (BK + 15) / 16), b(16, 16);
        gemm_bias<<<g, b>>>(xr, dfc1_w, dfc1_b, d512, BK, 512, HH); }
    ln_act<<<BK, BS>>>(d512, d512, 512, 1);

    {   dim3 g((4096 + 15) / 16, (BK + 15) / 16), b(16, 16);
        gemm_bias<<<g, b>>>(d512, dfc2_w, dfc2_b, d4096, BK, 4096, 512); }
    ln_act<<<BK, BS>>>(d4096, d4096, 4096, 1);

    dec_conv<64, 32, 8, false><<<nblk((long long)BK*16*16*32, BS), BS>>>(d4096, d1w, d1b, u1);
    ln_act<<<BK, BS>>>(u1, u1, 16*16*32, 1);
    dec_conv<32, 16, 16, false><<<nblk((long long)BK*32*32*16, BS), BS>>>(u1, d2w, d2b, u2);
    ln_act<<<BK, BS>>>(u2, u2, 32*32*16, 1);
    dec_conv<16, 1, 32, true><<<nblk((long long)BK*64*64, BS), BS>>>(u2, d3w, d3b, out_x);
}

// round 7
// speedup vs baseline: 15.8003x; 15.8003x over previous
#include <cuda_runtime.h>
#include <math.h>

// ---------------- problem constants ----------------
#define BK   384      // 48 * K
#define BB   48
#define KK   8
#define HH   250
#define EPSL 1e-5f

// ---------------- scratch (device globals, no allocs) ----------------
__device__ float g_e1[BK*32*32*16];
__device__ float g_e2[BK*16*16*32];
__device__ float g_e3[BK*8*8*64];
__device__ float g_h [BK*512];
__device__ float g_s1[BK*HH];
__device__ float g_pair[BB*KK*7*(2*HH)];
__device__ float g_core[BB*KK*7*HH];
__device__ float g_ctx [BB*KK*7*HH];
__device__ float g_a1  [BB*KK*7*100];
__device__ float g_att [BB*KK*7];
__device__ float g_eff [BK*HH];
__device__ float g_tot [BK*(2*HH+512)];
__device__ float g_ns  [BK*HH];
__device__ float g_xr  [BK*HH];
__device__ float g_d512[BK*512];
__device__ float g_d4096[BK*4096];
__device__ float g_u1[BK*16*16*32];
__device__ float g_u2[BK*32*32*16];
// transposed / folded weights
__device__ float g_c1wt[16*1*16];
__device__ float g_c2wt[16*16*32];
__device__ float g_c3wt[16*32*64];
__device__ float g_d1wf[16*64*32];
__device__ float g_d2wf[16*32*16];
__device__ float g_d3wf[16*16*1];

// ---------------- helpers ----------------
__device__ __forceinline__ void block_reduce2(float& a, float& b) {
    __shared__ float sa[32], sb[32];
    const unsigned m = 0xffffffffu;
    for (int o = 16; o > 0; o >>= 1) { a += __shfl_down_sync(m, a, o); b += __shfl_down_sync(m, b, o); }
    int lane = threadIdx.x & 31, wid = threadIdx.x >> 5;
    if (lane == 0) { sa[wid] = a; sb[wid] = b; }
    __syncthreads();
    int nw = (blockDim.x + 31) >> 5;
    if (wid == 0) {
        a = (lane < nw) ? sa[lane] : 0.f;
        b = (lane < nw) ? sb[lane] : 0.f;
        for (int o = 16; o > 0; o >>= 1) { a += __shfl_down_sync(m, a, o); b += __shfl_down_sync(m, b, o); }
        if (lane == 0) { sa[0] = a; sb[0] = b; }
    }
    __syncthreads();
    a = sa[0]; b = sb[0];
    __syncthreads();
}

__device__ __forceinline__ float sigm(float v) { return 1.f / (1.f + expf(-v)); }

// ---------------- weight precompute ----------------
// wt[((kh*4+kw)*CIN + i)*COUT + o] = w[((o*CIN + i)*4 + kh)*4 + kw]
template<int CIN, int COUT>
__global__ void transpose_w(const float* __restrict__ w, float* __restrict__ wt) {
    int idx = blockIdx.x * blockDim.x + threadIdx.x;
    const int total = 16 * CIN * COUT;
    if (idx >= total) return;
    int o = idx % COUT; int t = idx / COUT;
    int i = t % CIN;    t /= CIN;
    int kw = t % 4;     int kh = t / 4;
    wt[idx] = w[(((size_t)o * CIN + i) * 4 + kh) * 4 + kw];
}

// Folded decoder weights: wf[((((pa*2+pb)*2+sy)*2+sx)*CIN + i)*COUT + o]
//   = sum_{kw in G(pa,sy)} sum_{kh in G(pb,sx)} w[o][i][kh][kw]
// G(0,0)={0} G(0,1)={1,2,3} G(1,0)={0,1,2} G(1,1)={3}
template<int CIN, int COUT>
__global__ void fold_w(const float* __restrict__ w, float* __restrict__ wf) {
    int idx = blockIdx.x * blockDim.x + threadIdx.x;
    const int total = 16 * CIN * COUT;
    if (idx >= total) return;
    int o = idx % COUT; int t = idx / COUT;
    int i = t % CIN;    t /= CIN;
    int sx = t % 2;     t /= 2;
    int sy = t % 2;     t /= 2;
    int pb = t % 2;     int pa = t / 2;
    // FIXED group bounds: G(0,0)=[0,0] G(0,1)=[1,3] G(1,0)=[0,2] G(1,1)=[3,3]
    int kwlo = pa ? (sy ? 3 : 0) : (sy ? 1 : 0);
    int kwhi = pa ? (sy ? 3 : 2) : (sy ? 3 : 0);
    int khlo = pb ? (sx ? 3 : 0) : (sx ? 1 : 0);
    int khhi = pb ? (sx ? 3 : 2) : (sx ? 3 : 0);
    float s = 0.f;
    for (int kw = kwlo; kw <= kwhi; kw++)
        for (int kh = khlo; kh <= khhi; kh++)
            s += w[(((size_t)o * CIN + i) * 4 + kh) * 4 + kw];
    wf[idx] = s;
}

// ---------------- encoder conv (warp: lane=o, PW positions) ----------------
template<int CIN, int COUT, int WOUT>
__global__ void enc_conv2(const float* __restrict__ in, const float* __restrict__ wt,
                          const float* __restrict__ bias, float* __restrict__ out) {
    constexpr int WIN = 2 * WOUT;
    constexpr int OL  = (COUT < 32) ? COUT : 32;
    constexpr int PW  = 32 / OL;
    constexpr int NA  = (COUT + 31) / 32;
    constexpr int BPG = WOUT / PW;
    int wg = blockIdx.x * (blockDim.x >> 5) + (threadIdx.x >> 5);
    const int total_warps = BK * WOUT * BPG;
    if (wg >= total_warps) return;
    int lane = threadIdx.x & 31;
    int p = lane / OL, o = lane % OL;
    int bq = wg % BPG; int t = wg / BPG;
    int ap = t % WOUT; int n = t / WOUT;
    int bp = bq + p * BPG;

    float acc[NA];
    #pragma unroll
    for (int k = 0; k < NA; k++) acc[k] = bias[o + k * 32];

    #pragma unroll
    for (int kw = 0; kw < 4; kw++) {
        int a = 2 * ap - 1 + kw;
        if (a < 0 || a >= WIN) continue;
        #pragma unroll
        for (int kh = 0; kh < 4; kh++) {
            int bb = 2 * bp - 1 + kh;
            bool vb = (bb >= 0) && (bb < WIN);
            const float* xp = in + ((size_t)(n * WIN + a) * WIN + bb) * CIN;
            const float* wp = wt + (size_t)((kh * 4 + kw) * CIN) * COUT + o;
            if constexpr (CIN == 1) {
                float xv = vb ? xp[0] : 0.f;
                acc[0] += xv * wp[0];
            } else {
                #pragma unroll
                for (int iq = 0; iq < CIN / 4; iq++) {
                    float4 xv = vb ? *(const float4*)(xp + iq * 4) : make_float4(0.f,0.f,0.f,0.f);
                    const float* wq = wp + (size_t)iq * 4 * COUT;
                    float xs[4] = {xv.x, xv.y, xv.z, xv.w};
                    #pragma unroll
                    for (int e = 0; e < 4; e++) {
                        #pragma unroll
                        for (int k = 0; k < NA; k++)
                            acc[k] += xs[e] * wq[e * COUT + k * 32];
                    }
                }
            }
        }
    }
    float* op = out + ((size_t)(n * WOUT + ap) * WOUT + bp) * COUT + o;
    #pragma unroll
    for (int k = 0; k < NA; k++) op[k * 32] = acc[k];
}

// ---------------- decoder conv (folded 2x2) ----------------
template<int CIN, int COUT, int WIN>
__global__ void dec_conv2(const float* __restrict__ in, const float* __restrict__ wf,
                          const float* __restrict__ bias, float* __restrict__ out) {
    constexpr int WOUT = 2 * WIN;
    constexpr int OL  = (COUT < 32) ? COUT : 32;
    constexpr int PW  = 32 / OL;
    constexpr int BPG = WOUT / PW;
    int wg = blockIdx.x * (blockDim.x >> 5) + (threadIdx.x >> 5);
    const int total_warps = BK * WOUT * BPG;
    if (wg >= total_warps) return;
    int lane = threadIdx.x & 31;
    int p = lane / OL, o = lane % OL;
    int bq = wg % BPG; int t = wg / BPG;
    int ap = t % WOUT; int n = t / WOUT;
    int bp = bq + p * BPG;

    int pa = ap & 1, ma = ap >> 1;
    int pb = bp & 1, mb = bp >> 1;
    float acc = bias[o];

    #pragma unroll
    for (int sy = 0; sy < 2; sy++) {
        int as = ma + (pa ? sy : sy - 1);
        bool va = (as >= 0) && (as < WIN);
        #pragma unroll
        for (int sx = 0; sx < 2; sx++) {
            int bs = mb + (pb ? sx : sx - 1);
            bool v = va && (bs >= 0) && (bs < WIN);
            const float* xp = in + ((size_t)(n * WIN + as) * WIN + bs) * CIN;
            const float* wp = wf + (size_t)(((((pa * 2 + pb) * 2 + sy) * 2 + sx)) * CIN) * COUT + o;
            #pragma unroll
            for (int iq = 0; iq < CIN / 4; iq++) {
                float4 xv = v ? *(const float4*)(xp + iq * 4) : make_float4(0.f,0.f,0.f,0.f);
                const float* wq = wp + (size_t)iq * 4 * COUT;
                acc += xv.x * wq[0];
                acc += xv.y * wq[COUT];
                acc += xv.z * wq[2 * COUT];
                acc += xv.w * wq[3 * COUT];
            }
        }
    }
    out[((size_t)(n * WOUT + ap) * WOUT + bp) * COUT + o] = acc;
}

// ---------------- final decoder conv (COUT=1, CIN=16) + sigmoid ----------------
__global__ void dec_conv3_final(const float* __restrict__ in, const float* __restrict__ wf,
                                const float* __restrict__ bias, float* __restrict__ out) {
    constexpr int WIN = 32, WOUT = 64, CIN = 16;
    int idx = blockIdx.x * blockDim.x + threadIdx.x;
    if (idx >= BK * WOUT * WOUT) return;
    int bp = idx % WOUT; int t = idx / WOUT;
    int ap = t % WOUT;   int n = t / WOUT;
    int pa = ap & 1, ma = ap >> 1;
    int pb = bp & 1, mb = bp >> 1;
    float acc = bias[0];
    #pragma unroll
    for (int sy = 0; sy < 2; sy++) {
        int as = ma + (pa ? sy : sy - 1);
        bool va = (as >= 0) && (as < WIN);
        #pragma unroll
        for (int sx = 0; sx < 2; sx++) {
            int bs = mb + (pb ? sx : sx - 1);
            bool v = va && (bs >= 0) && (bs < WIN);
            const float* xp = in + ((size_t)(n * WIN + as) * WIN + bs) * CIN;
            const float* wq = wf + (((pa * 2 + pb) * 2 + sy) * 2 + sx) * CIN;
            #pragma unroll
            for (int iq = 0; iq < CIN / 4; iq++) {
                float4 xv = v ? *(const float4*)(xp + iq * 4) : make_float4(0.f,0.f,0.f,0.f);
                float4 wv = *(const float4*)(wq + iq * 4);
                acc += xv.x * wv.x; acc += xv.y * wv.y;
                acc += xv.z * wv.z; acc += xv.w * wv.w;
            }
        }
    }
    out[idx] = sigm(acc);
}

// ---------------- LayerNorm + activation (mode: 0=elu 1=relu 2=tanh) ----------------
__global__ void ln_act(const float* __restrict__ in, float* __restrict__ out, int C, int mode) {
    int r = blockIdx.x;
    const float* x = in + (size_t)r * C;
    float s = 0.f, ss = 0.f;
    for (int c = threadIdx.x; c < C; c += blockDim.x) { float v = x[c]; s += v; ss += v * v; }
    block_reduce2(s, ss);
    float mean = s / C;
    float var = ss / C - mean * mean;
    float inv = rsqrtf(var + EPSL);
    float* y = out + (size_t)r * C;
    for (int c = threadIdx.x; c < C; c += blockDim.x) {
        float v = (x[c] - mean) * inv;
        if (mode == 0)      v = (v > 0.f) ? v : expm1f(v);
        else if (mode == 1) v = fmaxf(v, 0.f);
        else                v = tanhf(v);
        y[c] = v;
    }
}

// ---------------- register-tiled GEMM: Y[M,N] = X[M,K] @ W[K,N] + b ----------------
__global__ void gemm_rt(const float* __restrict__ X, const float* __restrict__ W,
                        const float* __restrict__ bias, float* __restrict__ Y,
                        int M, int N, int Kd) {
    __shared__ __align__(16) float As[16][68];
    __shared__ __align__(16) float Bs[16][68];
    int tx = threadIdx.x, ty = threadIdx.y;
    int tid = ty * 16 + tx;
    int bm = blockIdx.y * 64, bn = blockIdx.x * 64;
    float acc[4][4];
    #pragma unroll
    for (int i = 0; i < 4; i++)
        #pragma unroll
        for (int j = 0; j < 4; j++) acc[i][j] = 0.f;

    for (int k0 = 0; k0 < Kd; k0 += 16) {
        #pragma unroll
        for (int u = 0; u < 4; u++) {
            int e = tid + u * 256;
            int r = e >> 4, kk = e & 15;
            As[kk][r] = (bm + r < M && k0 + kk < Kd) ? X[(size_t)(bm + r) * Kd + k0 + kk] : 0.f;
            int kb = e >> 6, c = e & 63;
            Bs[kb][c] = (k0 + kb < Kd && bn + c < N) ? W[(size_t)(k0 + kb) * N + bn + c] : 0.f;
        }
        __syncthreads();
        #pragma unroll
        for (int kk = 0; kk < 16; kk++) {
            float4 a4 = *(const float4*)&As[kk][ty * 4];
            float4 b4 = *(const float4*)&Bs[kk][tx * 4];
            float av[4] = {a4.x, a4.y, a4.z, a4.w};
            float bv[4] = {b4.x, b4.y, b4.z, b4.w};
            #pragma unroll
            for (int i = 0; i < 4; i++)
                #pragma unroll
                for (int j = 0; j < 4; j++) acc[i][j] += av[i] * bv[j];
        }
        __syncthreads();
    }
    #pragma unroll
    for (int i = 0; i < 4; i++) {
        int row = bm + ty * 4 + i;
        if (row >= M) continue;
        #pragma unroll
        for (int j = 0; j < 4; j++) {
            int col = bn + tx * 4 + j;
            if (col < N) Y[(size_t)row * N + col] = acc[i][j] + bias[col];
        }
    }
}

// ---------------- pair build ----------------
__global__ void build_pair(const float* __restrict__ s1, float* __restrict__ pair) {
    const int total = BB * KK * 7 * (2 * HH);
    for (int idx = blockIdx.x * blockDim.x + threadIdx.x; idx < total; idx += gridDim.x * blockDim.x) {
        int c = idx % (2 * HH);
        int r = idx / (2 * HH);
        int j = r % 7;  int t = r / 7;
        int i = t % KK; int bq = t / KK;
        int jj = (j < i) ? j : j + 1;
        float v;
        if (c < HH) v = s1[(size_t)(bq * KK + i) * HH + c];
        else        v = s1[(size_t)(bq * KK + jj) * HH + (c - HH)];
        pair[idx] = v;
    }
}

// ---------------- att2 ----------------
__global__ void att2_kernel(const float* __restrict__ a1, const float* __restrict__ w2,
                            const float* __restrict__ b2, float* __restrict__ att, int R) {
    int r = blockIdx.x * 4 + (threadIdx.x >> 5);
    int lane = threadIdx.x & 31;
    if (r >= R) return;
    float s = 0.f;
    for (int c = lane; c < 100; c += 32) s += a1[(size_t)r * 100 + c] * w2[c];
    for (int o = 16; o > 0; o >>= 1) s += __shfl_down_sync(0xffffffffu, s, o);
    if (lane == 0) att[r] = sigm(s + b2[0]);
}

// ---------------- effect ----------------
__global__ void effect_kernel(const float* __restrict__ ctx, const float* __restrict__ att,
                              float* __restrict__ eff) {
    int idx = blockIdx.x * blockDim.x + threadIdx.x;
    if (idx >= BK * HH) return;
    int h = idx % HH;
    int rbk = idx / HH;
    float acc = 0.f;
    #pragma unroll
    for (int j = 0; j < 7; j++) {
        int r = rbk * 7 + j;
        acc += ctx[(size_t)r * HH + h] * att[r];
    }
    eff[idx] = acc;
}

// ---------------- total build ----------------
__global__ void build_total(const float* __restrict__ s1, const float* __restrict__ eff,
                            const float* __restrict__ h, float* __restrict__ tot) {
    const int CT = 2 * HH + 512;
    const int total = BK * CT;
    for (int idx = blockIdx.x * blockDim.x + threadIdx.x; idx < total; idx += gridDim.x * blockDim.x) {
        int c = idx % CT;
        int r = idx / CT;
        float v;
        if (c < HH)            v = s1[(size_t)r * HH + c];
        else if (c < 2 * HH)   v = eff[(size_t)r * HH + (c - HH)];
        else                   v = h[(size_t)r * 512 + (c - 2 * HH)];
        tot[idx] = v;
    }
}

// ---------------- xr/state ----------------
__global__ void xr_state_kernel(const float* __restrict__ ns, float* __restrict__ xr,
                                float* __restrict__ st_out) {
    int r = blockIdx.x;
    const float* x = ns + (size_t)r * HH;
    float s = 0.f, ss = 0.f;
    for (int c = threadIdx.x; c < HH; c += blockDim.x) { float v = x[c]; s += v; ss += v * v; }
    block_reduce2(s, ss);
    float mean = s / HH;
    float var = ss / HH - mean * mean;
    float inv = rsqrtf(var + EPSL);
    for (int c = threadIdx.x; c < HH; c += blockDim.x) {
        float v = x[c];
        xr[(size_t)r * HH + c] = sigm((v - mean) * inv);
        st_out[(size_t)r * HH + c] = sigm(v);
    }
}

// ---------------- host side ----------------
static inline int nblk(long long total, int bs) { return (int)((total + bs - 1) / bs); }
static inline int wblk(long long warps) { return (int)((warps * 32 + 255) / 256); }

extern "C" void kernel_launch(void* const* d_in, const int* in_sizes, int n_in,
                              void* d_out, int out_size) {
    const float* x      = (const float*)d_in[0];
    const float* state  = (const float*)d_in[1];
    const float* c1w = (const float*)d_in[2];  const float* c1b = (const float*)d_in[3];
    const float* c2w = (const float*)d_in[4];  const float* c2b = (const float*)d_in[5];
    const float* c3w = (const float*)d_in[6];  const float* c3b = (const float*)d_in[7];
    const float* efc_w = (const float*)d_in[8];  const float* efc_b = (const float*)d_in[9];
    const float* renc_w = (const float*)d_in[10]; const float* renc_b = (const float*)d_in[11];
    const float* core_w = (const float*)d_in[12]; const float* core_b = (const float*)d_in[13];
    const float* ctx_w  = (const float*)d_in[14]; const float* ctx_b  = (const float*)d_in[15];
    const float* att1_w = (const float*)d_in[16]; const float* att1_b = (const float*)d_in[17];
    const float* att2_w = (const float*)d_in[18]; const float* att2_b = (const float*)d_in[19];
    const float* out_w  = (const float*)d_in[20]; const float* out_b  = (const float*)d_in[21];
    const float* dfc1_w = (const float*)d_in[22]; const float* dfc1_b = (const float*)d_in[23];
    const float* dfc2_w = (const float*)d_in[24]; const float* dfc2_b = (const float*)d_in[25];
    const float* d1w = (const float*)d_in[26]; const float* d1b = (const float*)d_in[27];
    const float* d2w = (const float*)d_in[28]; const float* d2b = (const float*)d_in[29];
    const float* d3w = (const float*)d_in[30]; const float* d3b = (const float*)d_in[31];

    float* out_x  = (float*)d_out;
    float* out_st = (float*)d_out + (size_t)BK * 4096;

    float *e1,*e2,*e3,*h,*s1,*pair,*core,*ctx,*a1,*att,*eff,*tot,*ns,*xr,*d512,*d4096,*u1,*u2;
    float *c1wt,*c2wt,*c3wt,*d1wf,*d2wf,*d3wf;
    cudaGetSymbolAddress((void**)&e1, g_e1);   cudaGetSymbolAddress((void**)&e2, g_e2);
    cudaGetSymbolAddress((void**)&e3, g_e3);   cudaGetSymbolAddress((void**)&h, g_h);
    cudaGetSymbolAddress((void**)&s1, g_s1);   cudaGetSymbolAddress((void**)&pair, g_pair);
    cudaGetSymbolAddress((void**)&core, g_core); cudaGetSymbolAddress((void**)&ctx, g_ctx);
    cudaGetSymbolAddress((void**)&a1, g_a1);   cudaGetSymbolAddress((void**)&att, g_att);
    cudaGetSymbolAddress((void**)&eff, g_eff); cudaGetSymbolAddress((void**)&tot, g_tot);
    cudaGetSymbolAddress((void**)&ns, g_ns);   cudaGetSymbolAddress((void**)&xr, g_xr);
    cudaGetSymbolAddress((void**)&d512, g_d512); cudaGetSymbolAddress((void**)&d4096, g_d4096);
    cudaGetSymbolAddress((void**)&u1, g_u1);   cudaGetSymbolAddress((void**)&u2, g_u2);
    cudaGetSymbolAddress((void**)&c1wt, g_c1wt); cudaGetSymbolAddress((void**)&c2wt, g_c2wt);
    cudaGetSymbolAddress((void**)&c3wt, g_c3wt); cudaGetSymbolAddress((void**)&d1wf, g_d1wf);
    cudaGetSymbolAddress((void**)&d2wf, g_d2wf); cudaGetSymbolAddress((void**)&d3wf, g_d3wf);

    const int BS = 256;

    // ---- weight precompute (tiny) ----
    transpose_w<1, 16><<<1, 256>>>(c1w, c1wt);
    transpose_w<16, 32><<<32, 256>>>(c2w, c2wt);
    transpose_w<32, 64><<<128, 256>>>(c3w, c3wt);
    fold_w<64, 32><<<128, 256>>>(d1w, d1wf);
    fold_w<32, 16><<<32, 256>>>(d2w, d2wf);
    fold_w<16, 1><<<1, 256>>>(d3w, d3wf);

    // ---- encoder ----
    enc_conv2<1, 16, 32><<<wblk((long long)BK*32*16), BS>>>(x, c1wt, c1b, e1);
    ln_act<<<BK, BS>>>(e1, e1, 32*32*16, 0);
    enc_conv2<16, 32, 16><<<wblk((long long)BK*16*16), BS>>>(e1, c2wt, c2b, e2);
    ln_act<<<BK, BS>>>(e2, e2, 16*16*32, 0);
    enc_conv2<32, 64, 8><<<wblk((long long)BK*8*8), BS>>>(e2, c3wt, c3b, e3);
    ln_act<<<BK, BS>>>(e3, e3, 8*8*64, 0);

    {   dim3 g((512 + 63) / 64, (BK + 63) / 64), b(16, 16);
        gemm_rt<<<g, b>>>(e3, efc_w, efc_b, h, BK, 512, 4096); }
    ln_act<<<BK, BS>>>(h, h, 512, 0);

    // ---- recurrent / attention core ----
    {   dim3 g((HH + 63) / 64, (BK + 63) / 64), b(16, 16);
        gemm_rt<<<g, b>>>(state, renc_w, renc_b, s1, BK, HH, HH); }
    ln_act<<<BK, BS>>>(s1, s1, HH, 1);

    build_pair<<<nblk((long long)BB*KK*7*(2*HH), BS), BS>>>(s1, pair);

    const int R = BB * KK * 7; // 2688
    {   dim3 g((HH + 63) / 64, (R + 63) / 64), b(16, 16);
        gemm_rt<<<g, b>>>(pair, core_w, core_b, core, R, HH, 2 * HH); }
    ln_act<<<R, BS>>>(core, core, HH, 1);

    {   dim3 g((HH + 63) / 64, (R + 63) / 64), b(16, 16);
        gemm_rt<<<g, b>>>(core, ctx_w, ctx_b, ctx, R, HH, HH); }
    ln_act<<<R, BS>>>(ctx, ctx, HH, 1);

    {   dim3 g((100 + 63) / 64, (R + 63) / 64), b(16, 16);
        gemm_rt<<<g, b>>>(core, att1_w, att1_b, a1, R, 100, HH); }
    ln_act<<<R, BS>>>(a1, a1, 100, 2);

    att2_kernel<<<(R + 3) / 4, 128>>>(a1, att2_w, att2_b, att, R);
    effect_kernel<<<nblk((long long)BK*HH, BS), BS>>>(ctx, att, eff);

    build_total<<<nblk((long long)BK*(2*HH+512), BS), BS>>>(s1, eff, h, tot);
    {   dim3 g((HH + 63) / 64, (BK + 63) / 64), b(16, 16);
        gemm_rt<<<g, b>>>(tot, out_w, out_b, ns, BK, HH, 2 * HH + 512); }

    xr_state_kernel<<<BK, BS>>>(ns, xr, out_st);

    // ---- decoder ----
    {   dim3 g((512 + 63) / 64, (BK + 63) / 64), b(16, 16);
        gemm_rt<<<g, b>>>(xr, dfc1_w, dfc1_b, d512, BK, 512, HH); }
    ln_act<<<BK, BS>>>(d512, d512, 512, 1);

    {   dim3 g((4096 + 63) / 64, (BK + 63) / 64), b(16, 16);
        gemm_rt<<<g, b>>>(d512, dfc2_w, dfc2_b, d4096, BK, 4096, 512); }
    ln_act<<<BK, BS>>>(d4096, d4096, 4096, 1);

    dec_conv2<64, 32, 8><<<wblk((long long)BK*16*16), BS>>>(d4096, d1wf, d1b, u1);
    ln_act<<<BK, BS>>>(u1, u1, 16*16*32, 1);
    dec_conv2<32, 16, 16><<<wblk((long long)BK*32*16), BS>>>(u1, d2wf, d2b, u2);
    ln_act<<<BK, BS>>>(u2, u2, 32*32*16, 1);
    dec_conv3_final<<<nblk((long long)BK*64*64, BS), BS>>>(u2, d3wf, d3b, out_x);
}